// round 15
// baseline (speedup 1.0000x reference)
#include <cuda_runtime.h>
#include <cuda_fp16.h>
#include <math.h>

#define NN  10000
#define FF  128
#define EE  640000
#define HID 64
#define TRW 32    // rows per GEMM tile
#define PKS 36    // padded row stride (floats) for transposed activations

typedef unsigned long long ull;

// ---------------- device scratch ----------------
__device__ __half g_Mh[NN * FF];   // per-node message, fp16 (edge path only)
__device__ float  g_agg[NN * FF];  // attention-weighted aggregate (fp32)
__device__ float  g_ssrc[NN];
__device__ float  g_sdst[NN];
__device__ float  g_v[FF];
__device__ int    g_deg[NN];
__device__ int    g_off[NN + 1];
__device__ int    g_rank[EE];
__device__ int2   g_edge[EE];      // {src, score_bits} sorted by dst

// ---------------- helpers ----------------
__device__ __forceinline__ ull pk(float lo, float hi) {
    ull r; asm("mov.b64 %0, {%1,%2};" : "=l"(r) : "f"(lo), "f"(hi)); return r;
}
__device__ __forceinline__ float2 upk(ull v) {
    float2 r; asm("mov.b64 {%0,%1}, %2;" : "=f"(r.x), "=f"(r.y) : "l"(v)); return r;
}
__device__ __forceinline__ void fma2(ull& d, ull a, ull b) {
    asm("fma.rn.f32x2 %0, %1, %2, %0;" : "+l"(d) : "l"(a), "l"(b));
}

// ---------------- prep: zero deg + v = node_kernel @ a1 ----------------
__global__ void k_prep(const float* __restrict__ nk, const float* __restrict__ attn) {
    if (blockIdx.x < 40) {
        int i = blockIdx.x * 256 + threadIdx.x;
        if (i < NN) g_deg[i] = 0;
    } else {
        int k = threadIdx.x;
        if (k < FF) {
            float s = 0.f;
            for (int c = 0; c < FF; c++) s += nk[k * FF + c] * attn[c];
            g_v[k] = s;
        }
    }
}

// histogram + per-edge rank (returned atomic)
__global__ void k_hist(const int4* __restrict__ dst4) {
    int i = blockIdx.x * blockDim.x + threadIdx.x;
    if (i < EE / 4) {
        int4 d = dst4[i];
        int4 r;
        r.x = atomicAdd(&g_deg[d.x], 1);
        r.y = atomicAdd(&g_deg[d.y], 1);
        r.z = atomicAdd(&g_deg[d.z], 1);
        r.w = atomicAdd(&g_deg[d.w], 1);
        reinterpret_cast<int4*>(g_rank)[i] = r;
    }
}

// warp-shuffle 2-level scan, 1024 threads, 1 block
__global__ void k_scan() {
    __shared__ int wsum[32], woff[32];
    int t = threadIdx.x, lane = t & 31, wid = t >> 5;
    const int CH = 10;
    int base = t * CH;
    int c[CH];
    int p = 0;
#pragma unroll
    for (int i = 0; i < CH; i++) {
        int idx = base + i;
        c[i] = (idx < NN) ? g_deg[idx] : 0;
        p += c[i];
    }
    int incl = p;
#pragma unroll
    for (int o = 1; o < 32; o <<= 1) {
        int v = __shfl_up_sync(0xffffffffu, incl, o);
        if (lane >= o) incl += v;
    }
    if (lane == 31) wsum[wid] = incl;
    __syncthreads();
    if (wid == 0) {
        int v = wsum[lane];
        int i2 = v;
#pragma unroll
        for (int o = 1; o < 32; o <<= 1) {
            int u = __shfl_up_sync(0xffffffffu, i2, o);
            if (lane >= o) i2 += u;
        }
        woff[lane] = i2 - v;
    }
    __syncthreads();
    int run = woff[wid] + incl - p;
#pragma unroll
    for (int i = 0; i < CH; i++) {
        int idx = base + i;
        if (idx < NN) {
            g_off[idx] = run;
            run += c[i];
        }
    }
    if (t == 1023) g_off[NN] = run;
}

// atomic-free scatter + fused score computation (runs AFTER k_node)
__global__ void k_scatter(const int4* __restrict__ src4, const int4* __restrict__ dst4) {
    int i = blockIdx.x * blockDim.x + threadIdx.x;
    if (i < EE / 4) {
        int4 s = src4[i];
        int4 d = dst4[i];
        int4 r = reinterpret_cast<const int4*>(g_rank)[i];
#pragma unroll
        for (int q = 0; q < 4; q++) {
            int ss = (q == 0) ? s.x : (q == 1) ? s.y : (q == 2) ? s.z : s.w;
            int dd = (q == 0) ? d.x : (q == 1) ? d.y : (q == 2) ? d.z : d.w;
            int rr = (q == 0) ? r.x : (q == 1) ? r.y : (q == 2) ? r.z : r.w;
            float e = g_ssrc[ss] + g_sdst[dd];
            e = e > 0.f ? e : 0.2f * e;
            g_edge[g_off[dd] + rr] = make_int2(ss, __float_as_int(e));
        }
    }
}

// ---- GEMM helpers: duplicated-W staging ----
// chunk = 32 k x 128 c, stored duplicated: wd[kk*256 + 2c] = wd[.. + 2c+1] = W[k][c]
__device__ __forceinline__ void ldW(float4* r, const float4* Wg, int ch, int t) {
    const float4* src = Wg + ch * 1024;
#pragma unroll
    for (int j = 0; j < 4; j++) r[j] = src[j * 256 + t];
}
__device__ __forceinline__ void stWdup(float* wd, const float4* r, int t) {
#pragma unroll
    for (int j = 0; j < 4; j++) {
        int p = j * 256 + t;
        int kk = p >> 5;             // p / 32  (32 float4 per k-row)
        int c  = (p & 31) << 2;      // (p%32)*4
        float4* dst = reinterpret_cast<float4*>(&wd[kk * 256 + 2 * c]);
        dst[0] = make_float4(r[j].x, r[j].x, r[j].y, r[j].y);
        dst[1] = make_float4(r[j].z, r[j].z, r[j].w, r[j].w);
    }
}

// inner compute over one 32-k chunk — plain C++ smem loads (compiler-ordered,
// vectorizable to LDS.128; correct with single-buffered wd across barriers)
__device__ __forceinline__ void gemm_chunk(ull acc[2][4], const float* wd,
                                           const float* actT, int kg0, int rb, int tc) {
#pragma unroll
    for (int kk = 0; kk < 32; kk++) {
        const ull* wp = reinterpret_cast<const ull*>(wd + kk * 256 + 8 * tc);
        ull b01 = wp[0], b23 = wp[1], b45 = wp[2], b67 = wp[3];
        const ull* ap = reinterpret_cast<const ull*>(actT + (kg0 + kk) * PKS + rb);
        ull a01 = ap[0], a23 = ap[1];
        fma2(acc[0][0], a01, b01); fma2(acc[0][1], a01, b23);
        fma2(acc[0][2], a01, b45); fma2(acc[0][3], a01, b67);
        fma2(acc[1][0], a23, b01); fma2(acc[1][1], a23, b23);
        fma2(acc[1][2], a23, b45); fma2(acc[1][3], a23, b67);
    }
}

// ---------------- node MLP with dup-W smem staging ----------------
__global__ void __launch_bounds__(256)
k_node(const float* __restrict__ h,  const float* __restrict__ W1,
       const float* __restrict__ b1, const float* __restrict__ W2,
       const float* __restrict__ b2, const float* __restrict__ attn) {
    extern __shared__ float sm[];
    float* actT = sm;             // [128 k][36 r]  (holds h, then t1)
    float* wd   = sm + FF * PKS;  // [32 k][256] duplicated W chunk (32KB)
    int t = threadIdx.x;
    int tc = t & 31, tw = t >> 5;
    int c0 = 4 * tc, rb = 4 * tw;
    int row0 = blockIdx.x * TRW;

    for (int i = t; i < TRW * FF; i += 256) {
        int c = i & 127, r = i >> 7;
        int gr = row0 + r;
        actT[c * PKS + r] = (gr < NN) ? h[gr * FF + c] : 0.f;
    }
    __syncthreads();

    // s_dst = h . a2 (while actT holds h)
    {
        float4 a2 = *reinterpret_cast<const float4*>(&attn[FF + c0]);
#pragma unroll
        for (int rr = 0; rr < 4; rr++) {
            int row = row0 + rb + rr;
            float p = actT[(c0 + 0) * PKS + rb + rr] * a2.x
                    + actT[(c0 + 1) * PKS + rb + rr] * a2.y
                    + actT[(c0 + 2) * PKS + rb + rr] * a2.z
                    + actT[(c0 + 3) * PKS + rb + rr] * a2.w;
#pragma unroll
            for (int o = 16; o > 0; o >>= 1) p += __shfl_xor_sync(0xffffffffu, p, o);
            if (tc == 0 && row < NN) g_sdst[row] = p;
        }
    }

    ull acc[2][4];
    float4 pf[4];

    // ================= GEMM1: t1 = relu(h @ W1 + b1) =================
    {
#pragma unroll
        for (int p = 0; p < 2; p++)
#pragma unroll
            for (int c = 0; c < 4; c++) acc[p][c] = 0ull;
        const float4* Wg = reinterpret_cast<const float4*>(W1);
        ldW(pf, Wg, 0, t);
        stWdup(wd, pf, t);
        __syncthreads();
        for (int ch = 0; ch < 4; ch++) {
            if (ch < 3) ldW(pf, Wg, ch + 1, t);
            gemm_chunk(acc, wd, actT, ch * 32, rb, tc);
            __syncthreads();
            if (ch < 3) { stWdup(wd, pf, t); __syncthreads(); }
        }
        float4 bb = *reinterpret_cast<const float4*>(&b1[c0]);
        float bv[4] = {bb.x, bb.y, bb.z, bb.w};
#pragma unroll
        for (int p = 0; p < 2; p++)
#pragma unroll
            for (int c = 0; c < 4; c++) {
                float2 v = upk(acc[p][c]);
                v.x = fmaxf(v.x + bv[c], 0.f);
                v.y = fmaxf(v.y + bv[c], 0.f);
                *reinterpret_cast<ull*>(&actT[(c0 + c) * PKS + rb + 2 * p]) = pk(v.x, v.y);
            }
    }
    __syncthreads();

    // ================= GEMM2: M = t1 @ W2 + b2 =================
    {
#pragma unroll
        for (int p = 0; p < 2; p++)
#pragma unroll
            for (int c = 0; c < 4; c++) acc[p][c] = 0ull;
        const float4* Wg = reinterpret_cast<const float4*>(W2);
        ldW(pf, Wg, 0, t);
        stWdup(wd, pf, t);
        __syncthreads();
        for (int ch = 0; ch < 4; ch++) {
            if (ch < 3) ldW(pf, Wg, ch + 1, t);
            gemm_chunk(acc, wd, actT, ch * 32, rb, tc);
            __syncthreads();
            if (ch < 3) { stWdup(wd, pf, t); __syncthreads(); }
        }
    }

    // epilogue: bias, fp16 store, ssrc dot
    {
        float4 bb = *reinterpret_cast<const float4*>(&b2[c0]);
        float4 vv = *reinterpret_cast<const float4*>(&g_v[c0]);
        uint2* Mh2 = reinterpret_cast<uint2*>(g_Mh);
#pragma unroll
        for (int p = 0; p < 2; p++) {
            int rlo = row0 + rb + 2 * p;
            int rhi = rlo + 1;
            float2 m0 = upk(acc[p][0]), m1 = upk(acc[p][1]), m2 = upk(acc[p][2]), m3 = upk(acc[p][3]);
            float4 lo = {m0.x + bb.x, m1.x + bb.y, m2.x + bb.z, m3.x + bb.w};
            float4 hi = {m0.y + bb.x, m1.y + bb.y, m2.y + bb.z, m3.y + bb.w};
            if (rlo < NN) {
                __half2 h0 = __floats2half2_rn(lo.x, lo.y);
                __half2 h1 = __floats2half2_rn(lo.z, lo.w);
                Mh2[rlo * 32 + tc] = make_uint2(*reinterpret_cast<unsigned*>(&h0),
                                                *reinterpret_cast<unsigned*>(&h1));
            }
            if (rhi < NN) {
                __half2 h0 = __floats2half2_rn(hi.x, hi.y);
                __half2 h1 = __floats2half2_rn(hi.z, hi.w);
                Mh2[rhi * 32 + tc] = make_uint2(*reinterpret_cast<unsigned*>(&h0),
                                                *reinterpret_cast<unsigned*>(&h1));
            }
            float plo = lo.x * vv.x + lo.y * vv.y + lo.z * vv.z + lo.w * vv.w;
            float phi = hi.x * vv.x + hi.y * vv.y + hi.z * vv.z + hi.w * vv.w;
#pragma unroll
            for (int o = 16; o > 0; o >>= 1) {
                plo += __shfl_xor_sync(0xffffffffu, plo, o);
                phi += __shfl_xor_sync(0xffffffffu, phi, o);
            }
            if (tc == 0) {
                if (rlo < NN) g_ssrc[rlo] = plo;
                if (rhi < NN) g_ssrc[rhi] = phi;
            }
        }
    }
}

// ---------------- edge aggregation: one warp per dst ----------------
__global__ void k_edge() {
    int w = (blockIdx.x * blockDim.x + threadIdx.x) >> 5;
    int lane = threadIdx.x & 31;
    if (w >= NN) return;
    int beg = g_off[w];
    int ne = g_off[w + 1] - beg;
    float4* aggp = reinterpret_cast<float4*>(&g_agg[w * FF]) + lane;
    if (ne == 0) {
        float4 z = {0.f, 0.f, 0.f, 0.f};
        *aggp = z;
        return;
    }
    float mx = -1e30f;
    for (int j = lane; j < ne; j += 32) {
        int2 p = g_edge[beg + j];
        mx = fmaxf(mx, __int_as_float(p.y));
    }
#pragma unroll
    for (int o = 16; o > 0; o >>= 1) mx = fmaxf(mx, __shfl_xor_sync(0xffffffffu, mx, o));

    float4 acc = {0.f, 0.f, 0.f, 0.f};
    float den = 0.f;
    const uint2* Mh2 = reinterpret_cast<const uint2*>(g_Mh);
    int j = 0;
    for (; j + 4 <= ne; j += 4) {
        int2 e0 = g_edge[beg + j],     e1 = g_edge[beg + j + 1];
        int2 e2 = g_edge[beg + j + 2], e3 = g_edge[beg + j + 3];
        float ex0 = __expf(__int_as_float(e0.y) - mx);
        float ex1 = __expf(__int_as_float(e1.y) - mx);
        float ex2 = __expf(__int_as_float(e2.y) - mx);
        float ex3 = __expf(__int_as_float(e3.y) - mx);
        uint2 u0 = Mh2[e0.x * 32 + lane], u1 = Mh2[e1.x * 32 + lane];
        uint2 u2 = Mh2[e2.x * 32 + lane], u3 = Mh2[e3.x * 32 + lane];
        den += (ex0 + ex1) + (ex2 + ex3);
        float2 a0 = __half22float2(*reinterpret_cast<__half2*>(&u0.x));
        float2 b0 = __half22float2(*reinterpret_cast<__half2*>(&u0.y));
        float2 a1 = __half22float2(*reinterpret_cast<__half2*>(&u1.x));
        float2 b1 = __half22float2(*reinterpret_cast<__half2*>(&u1.y));
        float2 a2 = __half22float2(*reinterpret_cast<__half2*>(&u2.x));
        float2 b2 = __half22float2(*reinterpret_cast<__half2*>(&u2.y));
        float2 a3 = __half22float2(*reinterpret_cast<__half2*>(&u3.x));
        float2 b3 = __half22float2(*reinterpret_cast<__half2*>(&u3.y));
        acc.x += ex0 * a0.x + ex1 * a1.x + ex2 * a2.x + ex3 * a3.x;
        acc.y += ex0 * a0.y + ex1 * a1.y + ex2 * a2.y + ex3 * a3.y;
        acc.z += ex0 * b0.x + ex1 * b1.x + ex2 * b2.x + ex3 * b3.x;
        acc.w += ex0 * b0.y + ex1 * b1.y + ex2 * b2.y + ex3 * b3.y;
    }
    for (; j < ne; j++) {
        int2 e0 = g_edge[beg + j];
        float ex = __expf(__int_as_float(e0.y) - mx);
        uint2 u0 = Mh2[e0.x * 32 + lane];
        float2 a0 = __half22float2(*reinterpret_cast<__half2*>(&u0.x));
        float2 b0 = __half22float2(*reinterpret_cast<__half2*>(&u0.y));
        den += ex;
        acc.x += ex * a0.x; acc.y += ex * a0.y;
        acc.z += ex * b0.x; acc.w += ex * b0.y;
    }
    float inv = 1.f / (den + 1e-9f);
    acc.x *= inv; acc.y *= inv; acc.z *= inv; acc.w *= inv;
    *aggp = acc;
}

// ---------------- update + readout, dup-W staging ----------------
__global__ void __launch_bounds__(256)
k_upd(const float* __restrict__ h,   const float* __restrict__ Wu,
      const float* __restrict__ bu,  const float* __restrict__ Wr1,
      const float* __restrict__ br1, const float* __restrict__ Wr2,
      const float* __restrict__ br2, float* __restrict__ out) {
    extern __shared__ float sm[];
    float* xsT = sm;                  // [256 k][36 r]; first 128 rows reused as hnT
    float* wd  = sm + 2 * FF * PKS;   // dup W chunk (32KB); also holds Wr1 stage
    int t = threadIdx.x;
    int tc = t & 31, tw = t >> 5;
    int c0 = 4 * tc, rb = 4 * tw;
    int row0 = blockIdx.x * TRW;

    for (int i = t; i < TRW * 256; i += 256) {
        int c = i & 255, r = i >> 8;
        int gr = row0 + r;
        float v = 0.f;
        if (gr < NN) v = (c < FF) ? g_agg[gr * FF + c] : h[gr * FF + (c - FF)];
        xsT[c * PKS + r] = v;
    }
    __syncthreads();

    ull acc[2][4];
#pragma unroll
    for (int p = 0; p < 2; p++)
#pragma unroll
        for (int c = 0; c < 4; c++) acc[p][c] = 0ull;
    float4 pf[4];

    // ======= GEMM-u: hn = relu([agg|h] @ Wu + bu), 8 chunks of 32 k =======
    {
        const float4* Wg = reinterpret_cast<const float4*>(Wu);
        ldW(pf, Wg, 0, t);
        stWdup(wd, pf, t);
        __syncthreads();
        for (int ch = 0; ch < 8; ch++) {
            if (ch < 7) ldW(pf, Wg, ch + 1, t);
            gemm_chunk(acc, wd, xsT, ch * 32, rb, tc);
            __syncthreads();
            if (ch < 7) { stWdup(wd, pf, t); __syncthreads(); }
        }
        float4 bb = *reinterpret_cast<const float4*>(&bu[c0]);
        float bv[4] = {bb.x, bb.y, bb.z, bb.w};
#pragma unroll
        for (int p = 0; p < 2; p++)
#pragma unroll
            for (int c = 0; c < 4; c++) {
                float2 v = upk(acc[p][c]);
                v.x = fmaxf(v.x + bv[c], 0.f);
                v.y = fmaxf(v.y + bv[c], 0.f);
                *reinterpret_cast<ull*>(&xsT[(c0 + c) * PKS + rb + 2 * p]) = pk(v.x, v.y);
            }
    }
    // stage full Wr1 (128x64 = 8192 floats = 32KB) into wd
    {
        const float4* Wg = reinterpret_cast<const float4*>(Wr1);
        float4* wb4 = reinterpret_cast<float4*>(wd);
        __syncthreads();
#pragma unroll
        for (int j = 0; j < 8; j++) wb4[j * 256 + t] = Wg[j * 256 + t];
        __syncthreads();
    }

    // ======= readout: r1 = relu(hn @ Wr1 + br1); out = r1 @ Wr2 + br2 =======
    int c1 = 2 * tc;
    ull ar[2][2];
    ar[0][0] = ar[0][1] = ar[1][0] = ar[1][1] = 0ull;
#pragma unroll 8
    for (int k = 0; k < FF; k++) {
        float2 bw = *reinterpret_cast<const float2*>(&wd[k * HID + c1]);
        const ull* ap = reinterpret_cast<const ull*>(xsT + k * PKS + rb);
        ull a01 = ap[0], a23 = ap[1];
        ull bx = pk(bw.x, bw.x), by = pk(bw.y, bw.y);
        fma2(ar[0][0], a01, bx); fma2(ar[0][1], a01, by);
        fma2(ar[1][0], a23, bx); fma2(ar[1][1], a23, by);
    }
    {
        float2 w2  = *reinterpret_cast<const float2*>(&Wr2[c1]);
        float2 bb1 = *reinterpret_cast<const float2*>(&br1[c1]);
        float br2v = br2[0];
#pragma unroll
        for (int p = 0; p < 2; p++) {
            int rlo = row0 + rb + 2 * p;
            int rhi = rlo + 1;
            float2 q0 = upk(ar[p][0]);
            float2 q1 = upk(ar[p][1]);
            float plo = fmaxf(q0.x + bb1.x, 0.f) * w2.x + fmaxf(q1.x + bb1.y, 0.f) * w2.y;
            float phi = fmaxf(q0.y + bb1.x, 0.f) * w2.x + fmaxf(q1.y + bb1.y, 0.f) * w2.y;
#pragma unroll
            for (int o = 16; o > 0; o >>= 1) {
                plo += __shfl_xor_sync(0xffffffffu, plo, o);
                phi += __shfl_xor_sync(0xffffffffu, phi, o);
            }
            if (tc == 0) {
                if (rlo < NN) out[rlo] = plo + br2v;
                if (rhi < NN) out[rhi] = phi + br2v;
            }
        }
    }
}

// ---------------- launch ----------------
extern "C" void kernel_launch(void* const* d_in, const int* in_sizes, int n_in,
                              void* d_out, int out_size) {
    const float* h    = (const float*)d_in[0];
    const int*   src  = (const int*)d_in[1];
    const int*   dst  = (const int*)d_in[2];
    const float* W1   = (const float*)d_in[3];
    const float* b1   = (const float*)d_in[4];
    const float* W2   = (const float*)d_in[5];
    const float* b2   = (const float*)d_in[6];
    const float* nk   = (const float*)d_in[7];
    const float* attn = (const float*)d_in[8];
    const float* Wu   = (const float*)d_in[9];
    const float* bu   = (const float*)d_in[10];
    const float* Wr1  = (const float*)d_in[11];
    const float* br1  = (const float*)d_in[12];
    const float* Wr2  = (const float*)d_in[13];
    const float* br2  = (const float*)d_in[14];
    float* out = (float*)d_out;

    const int smem_node = (FF * PKS + 8192) * sizeof(float);      // 51200
    const int smem_upd  = (2 * FF * PKS + 8192) * sizeof(float);  // 69632
    cudaFuncSetAttribute(k_node, cudaFuncAttributeMaxDynamicSharedMemorySize, smem_node);
    cudaFuncSetAttribute(k_upd,  cudaFuncAttributeMaxDynamicSharedMemorySize, smem_upd);

    k_prep<<<41, 256>>>(nk, attn);
    k_hist<<<(EE / 4 + 255) / 256, 256>>>((const int4*)dst);
    k_scan<<<1, 1024>>>();
    k_node<<<(NN + TRW - 1) / TRW, 256, smem_node>>>(h, W1, b1, W2, b2, attn);
    k_scatter<<<(EE / 4 + 255) / 256, 256>>>((const int4*)src, (const int4*)dst);
    k_edge<<<(NN * 32 + 255) / 256, 256>>>();
    k_upd<<<(NN + TRW - 1) / TRW, 256, smem_upd>>>(h, Wu, bu, Wr1, br1, Wr2, br2, out);
}

// round 16
// speedup vs baseline: 1.2789x; 1.2789x over previous
#include <cuda_runtime.h>
#include <cuda_fp16.h>
#include <math.h>

#define NN  10000
#define FF  128
#define EE  640000
#define HID 64
#define TRW 32    // rows per GEMM tile
#define PADD 68   // padded stride for duplicated activations: 64 (=2*TRW) + 4

typedef unsigned long long ull;

// ---------------- device scratch ----------------
__device__ __half g_Mh[NN * FF];   // per-node message, fp16 (edge path only)
__device__ float  g_agg[NN * FF];  // attention-weighted aggregate (fp32)
__device__ float  g_ssrc[NN];
__device__ float  g_sdst[NN];
__device__ float  g_v[FF];
__device__ int    g_deg[NN];
__device__ int    g_off[NN + 1];
__device__ int    g_rank[EE];
__device__ int2   g_edge[EE];      // {src, score_bits} sorted by dst

// ---------------- helpers ----------------
__device__ __forceinline__ ull pk(float lo, float hi) {
    ull r; asm("mov.b64 %0, {%1,%2};" : "=l"(r) : "f"(lo), "f"(hi)); return r;
}
__device__ __forceinline__ float2 upk(ull v) {
    float2 r; asm("mov.b64 {%0,%1}, %2;" : "=f"(r.x), "=f"(r.y) : "l"(v)); return r;
}
__device__ __forceinline__ void fma2(ull& d, ull a, ull b) {
    asm("fma.rn.f32x2 %0, %1, %2, %0;" : "+l"(d) : "l"(a), "l"(b));
}

// ---------------- prep: zero deg + v = node_kernel @ a1 ----------------
__global__ void k_prep(const float* __restrict__ nk, const float* __restrict__ attn) {
    if (blockIdx.x < 40) {
        int i = blockIdx.x * 256 + threadIdx.x;
        if (i < NN) g_deg[i] = 0;
    } else {
        int k = threadIdx.x;
        if (k < FF) {
            float s = 0.f;
            for (int c = 0; c < FF; c++) s += nk[k * FF + c] * attn[c];
            g_v[k] = s;
        }
    }
}

// histogram + per-edge rank (returned atomic)
__global__ void k_hist(const int4* __restrict__ dst4) {
    int i = blockIdx.x * blockDim.x + threadIdx.x;
    if (i < EE / 4) {
        int4 d = dst4[i];
        int4 r;
        r.x = atomicAdd(&g_deg[d.x], 1);
        r.y = atomicAdd(&g_deg[d.y], 1);
        r.z = atomicAdd(&g_deg[d.z], 1);
        r.w = atomicAdd(&g_deg[d.w], 1);
        reinterpret_cast<int4*>(g_rank)[i] = r;
    }
}

// warp-shuffle 2-level scan, 1024 threads, 1 block
__global__ void k_scan() {
    __shared__ int wsum[32], woff[32];
    int t = threadIdx.x, lane = t & 31, wid = t >> 5;
    const int CH = 10;
    int base = t * CH;
    int c[CH];
    int p = 0;
#pragma unroll
    for (int i = 0; i < CH; i++) {
        int idx = base + i;
        c[i] = (idx < NN) ? g_deg[idx] : 0;
        p += c[i];
    }
    int incl = p;
#pragma unroll
    for (int o = 1; o < 32; o <<= 1) {
        int v = __shfl_up_sync(0xffffffffu, incl, o);
        if (lane >= o) incl += v;
    }
    if (lane == 31) wsum[wid] = incl;
    __syncthreads();
    if (wid == 0) {
        int v = wsum[lane];
        int i2 = v;
#pragma unroll
        for (int o = 1; o < 32; o <<= 1) {
            int u = __shfl_up_sync(0xffffffffu, i2, o);
            if (lane >= o) i2 += u;
        }
        woff[lane] = i2 - v;
    }
    __syncthreads();
    int run = woff[wid] + incl - p;
#pragma unroll
    for (int i = 0; i < CH; i++) {
        int idx = base + i;
        if (idx < NN) {
            g_off[idx] = run;
            run += c[i];
        }
    }
    if (t == 1023) g_off[NN] = run;
}

// atomic-free scatter + fused score computation (runs AFTER k_node)
__global__ void k_scatter(const int4* __restrict__ src4, const int4* __restrict__ dst4) {
    int i = blockIdx.x * blockDim.x + threadIdx.x;
    if (i < EE / 4) {
        int4 s = src4[i];
        int4 d = dst4[i];
        int4 r = reinterpret_cast<const int4*>(g_rank)[i];
#pragma unroll
        for (int q = 0; q < 4; q++) {
            int ss = (q == 0) ? s.x : (q == 1) ? s.y : (q == 2) ? s.z : s.w;
            int dd = (q == 0) ? d.x : (q == 1) ? d.y : (q == 2) ? d.z : d.w;
            int rr = (q == 0) ? r.x : (q == 1) ? r.y : (q == 2) ? r.z : r.w;
            float e = g_ssrc[ss] + g_sdst[dd];
            e = e > 0.f ? e : 0.2f * e;
            g_edge[g_off[dd] + rr] = make_int2(ss, __float_as_int(e));
        }
    }
}

// ---- GEMM helpers: PLAIN W staging (R8-proven, double-buffered) ----
__device__ __forceinline__ void ldW(float4* r, const float4* Wg, int ch, int t) {
    const float4* src = Wg + ch * 1024;
#pragma unroll
    for (int j = 0; j < 4; j++) r[j] = src[j * 256 + t];
}
__device__ __forceinline__ void stW(float* wb, const float4* r, int t) {
    float4* dst = reinterpret_cast<float4*>(wb);
#pragma unroll
    for (int j = 0; j < 4; j++) dst[j * 256 + t] = r[j];
}

// inner compute over one 32-k chunk.
// acc[r][j]: r = row in pair, j = column pair {4cg+2j} (j<2) / {64+4cg+2(j-2)} (j>=2)
// W read: 2 conflict-free LDS.128; A read: 1 broadcast LDS.128 from duplicated tile.
__device__ __forceinline__ void gemm_chunk(ull acc[2][4], const float* wc,
                                           const float* actTd, int kg0, int aoff, int cg) {
#pragma unroll
    for (int kk = 0; kk < 32; kk++) {
        const float* wrow = wc + kk * FF;
        const ull* wp0 = reinterpret_cast<const ull*>(wrow + 4 * cg);
        const ull* wp1 = reinterpret_cast<const ull*>(wrow + 64 + 4 * cg);
        ull b0 = wp0[0], b1 = wp0[1];
        ull b2 = wp1[0], b3 = wp1[1];
        const ull* ap = reinterpret_cast<const ull*>(actTd + (kg0 + kk) * PADD + aoff);
        ull a0 = ap[0], a1 = ap[1];   // (aR0,aR0), (aR1,aR1)
        fma2(acc[0][0], a0, b0); fma2(acc[0][1], a0, b1);
        fma2(acc[0][2], a0, b2); fma2(acc[0][3], a0, b3);
        fma2(acc[1][0], a1, b0); fma2(acc[1][1], a1, b1);
        fma2(acc[1][2], a1, b2); fma2(acc[1][3], a1, b3);
    }
}

// ---------------- node MLP ----------------
// 32-row x 128-col tile, 256 threads. Thread = 2 rows x 8 cols
// (cols 4cg..4cg+3 and 64+4cg..64+4cg+3), cg = lane&15, rgrp = lane>>4.
__global__ void __launch_bounds__(256)
k_node(const float* __restrict__ h,  const float* __restrict__ W1,
       const float* __restrict__ b1, const float* __restrict__ W2,
       const float* __restrict__ b2, const float* __restrict__ attn) {
    extern __shared__ float sm[];
    float* actTd = sm;               // [128 k][PADD] duplicated rows (h, then t1)
    float* wb    = sm + FF * PADD;   // [2][32*128] plain W chunks
    int t = threadIdx.x;
    int lane = t & 31, tw = t >> 5;
    int cg = lane & 15, rgrp = lane >> 4;
    int R0 = 4 * tw + 2 * rgrp;      // first of thread's two rows (tile-local)
    int aoff = 2 * R0;               // duplicated-row float offset
    int cA = 4 * cg, cB = 64 + 4 * cg;
    int row0 = blockIdx.x * TRW;

    // load h tile, duplicated per row
    for (int i = t; i < TRW * FF; i += 256) {
        int c = i & 127, r = i >> 7;
        int gr = row0 + r;
        float v = (gr < NN) ? h[gr * FF + c] : 0.f;
        actTd[c * PADD + 2 * r]     = v;
        actTd[c * PADD + 2 * r + 1] = v;
    }
    __syncthreads();

    // s_dst = h . a2 (while actTd holds h)
    {
        float4 a2A = *reinterpret_cast<const float4*>(&attn[FF + cA]);
        float4 a2B = *reinterpret_cast<const float4*>(&attn[FF + cB]);
#pragma unroll
        for (int r = 0; r < 2; r++) {
            int od = aoff + 2 * r;
            float p = actTd[(cA + 0) * PADD + od] * a2A.x
                    + actTd[(cA + 1) * PADD + od] * a2A.y
                    + actTd[(cA + 2) * PADD + od] * a2A.z
                    + actTd[(cA + 3) * PADD + od] * a2A.w
                    + actTd[(cB + 0) * PADD + od] * a2B.x
                    + actTd[(cB + 1) * PADD + od] * a2B.y
                    + actTd[(cB + 2) * PADD + od] * a2B.z
                    + actTd[(cB + 3) * PADD + od] * a2B.w;
#pragma unroll
            for (int o = 8; o > 0; o >>= 1) p += __shfl_xor_sync(0xffffffffu, p, o);
            int row = row0 + R0 + r;
            if (cg == 0 && row < NN) g_sdst[row] = p;
        }
    }

    ull acc[2][4];
    float4 pf[4];

    // ================= GEMM1: t1 = relu(h @ W1 + b1) =================
    {
#pragma unroll
        for (int p = 0; p < 2; p++)
#pragma unroll
            for (int c = 0; c < 4; c++) acc[p][c] = 0ull;
        const float4* Wg = reinterpret_cast<const float4*>(W1);
        ldW(pf, Wg, 0, t);
        stW(wb, pf, t);
        __syncthreads();
        for (int ch = 0; ch < 4; ch++) {
            if (ch < 3) ldW(pf, Wg, ch + 1, t);
            gemm_chunk(acc, wb + (ch & 1) * 4096, actTd, ch * 32, aoff, cg);
            __syncthreads();
            if (ch < 3) { stW(wb + ((ch + 1) & 1) * 4096, pf, t); __syncthreads(); }
        }
        // epilogue: relu+bias -> overwrite actTd with t1 (duplicated rows)
        float4 bA = *reinterpret_cast<const float4*>(&b1[cA]);
        float4 bB = *reinterpret_cast<const float4*>(&b1[cB]);
        float2 v00 = upk(acc[0][0]), v01 = upk(acc[0][1]), v02 = upk(acc[0][2]), v03 = upk(acc[0][3]);
        float2 v10 = upk(acc[1][0]), v11 = upk(acc[1][1]), v12 = upk(acc[1][2]), v13 = upk(acc[1][3]);
        float4* a4;
        a4 = reinterpret_cast<float4*>(&actTd[(cA + 0) * PADD + aoff]);
        *a4 = make_float4(fmaxf(v00.x + bA.x, 0.f), fmaxf(v00.x + bA.x, 0.f),
                          fmaxf(v10.x + bA.x, 0.f), fmaxf(v10.x + bA.x, 0.f));
        a4 = reinterpret_cast<float4*>(&actTd[(cA + 1) * PADD + aoff]);
        *a4 = make_float4(fmaxf(v00.y + bA.y, 0.f), fmaxf(v00.y + bA.y, 0.f),
                          fmaxf(v10.y + bA.y, 0.f), fmaxf(v10.y + bA.y, 0.f));
        a4 = reinterpret_cast<float4*>(&actTd[(cA + 2) * PADD + aoff]);
        *a4 = make_float4(fmaxf(v01.x + bA.z, 0.f), fmaxf(v01.x + bA.z, 0.f),
                          fmaxf(v11.x + bA.z, 0.f), fmaxf(v11.x + bA.z, 0.f));
        a4 = reinterpret_cast<float4*>(&actTd[(cA + 3) * PADD + aoff]);
        *a4 = make_float4(fmaxf(v01.y + bA.w, 0.f), fmaxf(v01.y + bA.w, 0.f),
                          fmaxf(v11.y + bA.w, 0.f), fmaxf(v11.y + bA.w, 0.f));
        a4 = reinterpret_cast<float4*>(&actTd[(cB + 0) * PADD + aoff]);
        *a4 = make_float4(fmaxf(v02.x + bB.x, 0.f), fmaxf(v02.x + bB.x, 0.f),
                          fmaxf(v12.x + bB.x, 0.f), fmaxf(v12.x + bB.x, 0.f));
        a4 = reinterpret_cast<float4*>(&actTd[(cB + 1) * PADD + aoff]);
        *a4 = make_float4(fmaxf(v02.y + bB.y, 0.f), fmaxf(v02.y + bB.y, 0.f),
                          fmaxf(v12.y + bB.y, 0.f), fmaxf(v12.y + bB.y, 0.f));
        a4 = reinterpret_cast<float4*>(&actTd[(cB + 2) * PADD + aoff]);
        *a4 = make_float4(fmaxf(v03.x + bB.z, 0.f), fmaxf(v03.x + bB.z, 0.f),
                          fmaxf(v13.x + bB.z, 0.f), fmaxf(v13.x + bB.z, 0.f));
        a4 = reinterpret_cast<float4*>(&actTd[(cB + 3) * PADD + aoff]);
        *a4 = make_float4(fmaxf(v03.y + bB.w, 0.f), fmaxf(v03.y + bB.w, 0.f),
                          fmaxf(v13.y + bB.w, 0.f), fmaxf(v13.y + bB.w, 0.f));
    }
    __syncthreads();

    // ================= GEMM2: M = t1 @ W2 + b2 =================
    {
#pragma unroll
        for (int p = 0; p < 2; p++)
#pragma unroll
            for (int c = 0; c < 4; c++) acc[p][c] = 0ull;
        const float4* Wg = reinterpret_cast<const float4*>(W2);
        ldW(pf, Wg, 0, t);
        stW(wb, pf, t);
        __syncthreads();
        for (int ch = 0; ch < 4; ch++) {
            if (ch < 3) ldW(pf, Wg, ch + 1, t);
            gemm_chunk(acc, wb + (ch & 1) * 4096, actTd, ch * 32, aoff, cg);
            __syncthreads();
            if (ch < 3) { stW(wb + ((ch + 1) & 1) * 4096, pf, t); __syncthreads(); }
        }
    }

    // epilogue: bias, fp16 store, ssrc dot
    {
        float4 bA = *reinterpret_cast<const float4*>(&b2[cA]);
        float4 bB = *reinterpret_cast<const float4*>(&b2[cB]);
        float4 vA = *reinterpret_cast<const float4*>(&g_v[cA]);
        float4 vB = *reinterpret_cast<const float4*>(&g_v[cB]);
#pragma unroll
        for (int r = 0; r < 2; r++) {
            int row = row0 + R0 + r;
            float2 m0 = upk(acc[r][0]), m1 = upk(acc[r][1]);
            float2 m2 = upk(acc[r][2]), m3 = upk(acc[r][3]);
            float4 mA = {m0.x + bA.x, m0.y + bA.y, m1.x + bA.z, m1.y + bA.w};
            float4 mB = {m2.x + bB.x, m2.y + bB.y, m3.x + bB.z, m3.y + bB.w};
            if (row < NN) {
                __half2 hA0 = __floats2half2_rn(mA.x, mA.y);
                __half2 hA1 = __floats2half2_rn(mA.z, mA.w);
                __half2 hB0 = __floats2half2_rn(mB.x, mB.y);
                __half2 hB1 = __floats2half2_rn(mB.z, mB.w);
                *reinterpret_cast<uint2*>(&g_Mh[row * FF + cA]) =
                    make_uint2(*reinterpret_cast<unsigned*>(&hA0), *reinterpret_cast<unsigned*>(&hA1));
                *reinterpret_cast<uint2*>(&g_Mh[row * FF + cB]) =
                    make_uint2(*reinterpret_cast<unsigned*>(&hB0), *reinterpret_cast<unsigned*>(&hB1));
            }
            float p = mA.x * vA.x + mA.y * vA.y + mA.z * vA.z + mA.w * vA.w
                    + mB.x * vB.x + mB.y * vB.y + mB.z * vB.z + mB.w * vB.w;
#pragma unroll
            for (int o = 8; o > 0; o >>= 1) p += __shfl_xor_sync(0xffffffffu, p, o);
            if (cg == 0 && row < NN) g_ssrc[row] = p;
        }
    }
}

// ---------------- edge aggregation: one warp per dst ----------------
__global__ void k_edge() {
    int w = (blockIdx.x * blockDim.x + threadIdx.x) >> 5;
    int lane = threadIdx.x & 31;
    if (w >= NN) return;
    int beg = g_off[w];
    int ne = g_off[w + 1] - beg;
    float4* aggp = reinterpret_cast<float4*>(&g_agg[w * FF]) + lane;
    if (ne == 0) {
        float4 z = {0.f, 0.f, 0.f, 0.f};
        *aggp = z;
        return;
    }
    float mx = -1e30f;
    for (int j = lane; j < ne; j += 32) {
        int2 p = g_edge[beg + j];
        mx = fmaxf(mx, __int_as_float(p.y));
    }
#pragma unroll
    for (int o = 16; o > 0; o >>= 1) mx = fmaxf(mx, __shfl_xor_sync(0xffffffffu, mx, o));

    float4 acc = {0.f, 0.f, 0.f, 0.f};
    float den = 0.f;
    const uint2* Mh2 = reinterpret_cast<const uint2*>(g_Mh);
    int j = 0;
    for (; j + 4 <= ne; j += 4) {
        int2 e0 = g_edge[beg + j],     e1 = g_edge[beg + j + 1];
        int2 e2 = g_edge[beg + j + 2], e3 = g_edge[beg + j + 3];
        float ex0 = __expf(__int_as_float(e0.y) - mx);
        float ex1 = __expf(__int_as_float(e1.y) - mx);
        float ex2 = __expf(__int_as_float(e2.y) - mx);
        float ex3 = __expf(__int_as_float(e3.y) - mx);
        uint2 u0 = Mh2[e0.x * 32 + lane], u1 = Mh2[e1.x * 32 + lane];
        uint2 u2 = Mh2[e2.x * 32 + lane], u3 = Mh2[e3.x * 32 + lane];
        den += (ex0 + ex1) + (ex2 + ex3);
        float2 a0 = __half22float2(*reinterpret_cast<__half2*>(&u0.x));
        float2 b0 = __half22float2(*reinterpret_cast<__half2*>(&u0.y));
        float2 a1 = __half22float2(*reinterpret_cast<__half2*>(&u1.x));
        float2 b1 = __half22float2(*reinterpret_cast<__half2*>(&u1.y));
        float2 a2 = __half22float2(*reinterpret_cast<__half2*>(&u2.x));
        float2 b2 = __half22float2(*reinterpret_cast<__half2*>(&u2.y));
        float2 a3 = __half22float2(*reinterpret_cast<__half2*>(&u3.x));
        float2 b3 = __half22float2(*reinterpret_cast<__half2*>(&u3.y));
        acc.x += ex0 * a0.x + ex1 * a1.x + ex2 * a2.x + ex3 * a3.x;
        acc.y += ex0 * a0.y + ex1 * a1.y + ex2 * a2.y + ex3 * a3.y;
        acc.z += ex0 * b0.x + ex1 * b1.x + ex2 * b2.x + ex3 * b3.x;
        acc.w += ex0 * b0.y + ex1 * b1.y + ex2 * b2.y + ex3 * b3.y;
    }
    for (; j < ne; j++) {
        int2 e0 = g_edge[beg + j];
        float ex = __expf(__int_as_float(e0.y) - mx);
        uint2 u0 = Mh2[e0.x * 32 + lane];
        float2 a0 = __half22float2(*reinterpret_cast<__half2*>(&u0.x));
        float2 b0 = __half22float2(*reinterpret_cast<__half2*>(&u0.y));
        den += ex;
        acc.x += ex * a0.x; acc.y += ex * a0.y;
        acc.z += ex * b0.x; acc.w += ex * b0.y;
    }
    float inv = 1.f / (den + 1e-9f);
    acc.x *= inv; acc.y *= inv; acc.z *= inv; acc.w *= inv;
    *aggp = acc;
}

// ---------------- update + readout ----------------
__global__ void __launch_bounds__(256)
k_upd(const float* __restrict__ h,   const float* __restrict__ Wu,
      const float* __restrict__ bu,  const float* __restrict__ Wr1,
      const float* __restrict__ br1, const float* __restrict__ Wr2,
      const float* __restrict__ br2, float* __restrict__ out) {
    extern __shared__ float sm[];
    float* xsTd = sm;                  // [256 k][PADD] duplicated; first 128 reused as hn
    float* wb   = sm + 2 * FF * PADD;  // [2][32*128]; also holds full Wr1 (32KB)
    int t = threadIdx.x;
    int lane = t & 31, tw = t >> 5;
    int cg = lane & 15, rgrp = lane >> 4;
    int R0 = 4 * tw + 2 * rgrp;
    int aoff = 2 * R0;
    int cA = 4 * cg, cB = 64 + 4 * cg;
    int row0 = blockIdx.x * TRW;

    for (int i = t; i < TRW * 256; i += 256) {
        int c = i & 255, r = i >> 8;
        int gr = row0 + r;
        float v = 0.f;
        if (gr < NN) v = (c < FF) ? g_agg[gr * FF + c] : h[gr * FF + (c - FF)];
        xsTd[c * PADD + 2 * r]     = v;
        xsTd[c * PADD + 2 * r + 1] = v;
    }
    __syncthreads();

    ull acc[2][4];
#pragma unroll
    for (int p = 0; p < 2; p++)
#pragma unroll
        for (int c = 0; c < 4; c++) acc[p][c] = 0ull;
    float4 pf[4];

    // ======= GEMM-u: hn = relu([agg|h] @ Wu + bu), 8 chunks of 32 k =======
    {
        const float4* Wg = reinterpret_cast<const float4*>(Wu);
        ldW(pf, Wg, 0, t);
        stW(wb, pf, t);
        __syncthreads();
        for (int ch = 0; ch < 8; ch++) {
            if (ch < 7) ldW(pf, Wg, ch + 1, t);
            gemm_chunk(acc, wb + (ch & 1) * 4096, xsTd, ch * 32, aoff, cg);
            __syncthreads();
            if (ch < 7) { stW(wb + ((ch + 1) & 1) * 4096, pf, t); __syncthreads(); }
        }
        // epilogue -> write hn duplicated into xsTd front region
        float4 bA = *reinterpret_cast<const float4*>(&bu[cA]);
        float4 bB = *reinterpret_cast<const float4*>(&bu[cB]);
        float2 v00 = upk(acc[0][0]), v01 = upk(acc[0][1]), v02 = upk(acc[0][2]), v03 = upk(acc[0][3]);
        float2 v10 = upk(acc[1][0]), v11 = upk(acc[1][1]), v12 = upk(acc[1][2]), v13 = upk(acc[1][3]);
        float4* a4;
        a4 = reinterpret_cast<float4*>(&xsTd[(cA + 0) * PADD + aoff]);
        *a4 = make_float4(fmaxf(v00.x + bA.x, 0.f), fmaxf(v00.x + bA.x, 0.f),
                          fmaxf(v10.x + bA.x, 0.f), fmaxf(v10.x + bA.x, 0.f));
        a4 = reinterpret_cast<float4*>(&xsTd[(cA + 1) * PADD + aoff]);
        *a4 = make_float4(fmaxf(v00.y + bA.y, 0.f), fmaxf(v00.y + bA.y, 0.f),
                          fmaxf(v10.y + bA.y, 0.f), fmaxf(v10.y + bA.y, 0.f));
        a4 = reinterpret_cast<float4*>(&xsTd[(cA + 2) * PADD + aoff]);
        *a4 = make_float4(fmaxf(v01.x + bA.z, 0.f), fmaxf(v01.x + bA.z, 0.f),
                          fmaxf(v11.x + bA.z, 0.f), fmaxf(v11.x + bA.z, 0.f));
        a4 = reinterpret_cast<float4*>(&xsTd[(cA + 3) * PADD + aoff]);
        *a4 = make_float4(fmaxf(v01.y + bA.w, 0.f), fmaxf(v01.y + bA.w, 0.f),
                          fmaxf(v11.y + bA.w, 0.f), fmaxf(v11.y + bA.w, 0.f));
        a4 = reinterpret_cast<float4*>(&xsTd[(cB + 0) * PADD + aoff]);
        *a4 = make_float4(fmaxf(v02.x + bB.x, 0.f), fmaxf(v02.x + bB.x, 0.f),
                          fmaxf(v12.x + bB.x, 0.f), fmaxf(v12.x + bB.x, 0.f));
        a4 = reinterpret_cast<float4*>(&xsTd[(cB + 1) * PADD + aoff]);
        *a4 = make_float4(fmaxf(v02.y + bB.y, 0.f), fmaxf(v02.y + bB.y, 0.f),
                          fmaxf(v12.y + bB.y, 0.f), fmaxf(v12.y + bB.y, 0.f));
        a4 = reinterpret_cast<float4*>(&xsTd[(cB + 2) * PADD + aoff]);
        *a4 = make_float4(fmaxf(v03.x + bB.z, 0.f), fmaxf(v03.x + bB.z, 0.f),
                          fmaxf(v13.x + bB.z, 0.f), fmaxf(v13.x + bB.z, 0.f));
        a4 = reinterpret_cast<float4*>(&xsTd[(cB + 3) * PADD + aoff]);
        *a4 = make_float4(fmaxf(v03.y + bB.w, 0.f), fmaxf(v03.y + bB.w, 0.f),
                          fmaxf(v13.y + bB.w, 0.f), fmaxf(v13.y + bB.w, 0.f));
    }
    __syncthreads();
    // stage full Wr1 (128x64 = 8192 floats = 32KB) into wb
    {
        const float4* Wg = reinterpret_cast<const float4*>(Wr1);
        float4* wb4 = reinterpret_cast<float4*>(wb);
#pragma unroll
        for (int j = 0; j < 8; j++) wb4[j * 256 + t] = Wg[j * 256 + t];
    }
    __syncthreads();

    // ======= readout: r1 = relu(hn @ Wr1 + br1); out = r1 @ Wr2 + br2 =======
    // thread cols: 4cg..4cg+3 of HID=64
    ull ar[2][2];
    ar[0][0] = ar[0][1] = ar[1][0] = ar[1][1] = 0ull;
#pragma unroll 8
    for (int k = 0; k < FF; k++) {
        const ull* wp = reinterpret_cast<const ull*>(wb + k * HID + cA);
        ull b0 = wp[0], b1 = wp[1];
        const ull* ap = reinterpret_cast<const ull*>(xsTd + k * PADD + aoff);
        ull a0 = ap[0], a1 = ap[1];
        fma2(ar[0][0], a0, b0); fma2(ar[0][1], a0, b1);
        fma2(ar[1][0], a1, b0); fma2(ar[1][1], a1, b1);
    }
    {
        float4 w2v  = *reinterpret_cast<const float4*>(&Wr2[cA]);
        float4 bb1v = *reinterpret_cast<const float4*>(&br1[cA]);
        float br2v = br2[0];
#pragma unroll
        for (int r = 0; r < 2; r++) {
            int row = row0 + R0 + r;
            float2 q0 = upk(ar[r][0]);
            float2 q1 = upk(ar[r][1]);
            float p = fmaxf(q0.x + bb1v.x, 0.f) * w2v.x + fmaxf(q0.y + bb1v.y, 0.f) * w2v.y
                    + fmaxf(q1.x + bb1v.z, 0.f) * w2v.z + fmaxf(q1.y + bb1v.w, 0.f) * w2v.w;
#pragma unroll
            for (int o = 8; o > 0; o >>= 1) p += __shfl_xor_sync(0xffffffffu, p, o);
            if (cg == 0 && row < NN) out[row] = p + br2v;
        }
    }
}

// ---------------- launch ----------------
extern "C" void kernel_launch(void* const* d_in, const int* in_sizes, int n_in,
                              void* d_out, int out_size) {
    const float* h    = (const float*)d_in[0];
    const int*   src  = (const int*)d_in[1];
    const int*   dst  = (const int*)d_in[2];
    const float* W1   = (const float*)d_in[3];
    const float* b1   = (const float*)d_in[4];
    const float* W2   = (const float*)d_in[5];
    const float* b2   = (const float*)d_in[6];
    const float* nk   = (const float*)d_in[7];
    const float* attn = (const float*)d_in[8];
    const float* Wu   = (const float*)d_in[9];
    const float* bu   = (const float*)d_in[10];
    const float* Wr1  = (const float*)d_in[11];
    const float* br1  = (const float*)d_in[12];
    const float* Wr2  = (const float*)d_in[13];
    const float* br2  = (const float*)d_in[14];
    float* out = (float*)d_out;

    const int smem_node = (FF * PADD + 2 * 4096) * sizeof(float);      // 67584
    const int smem_upd  = (2 * FF * PADD + 2 * 4096) * sizeof(float);  // 102400
    cudaFuncSetAttribute(k_node, cudaFuncAttributeMaxDynamicSharedMemorySize, smem_node);
    cudaFuncSetAttribute(k_upd,  cudaFuncAttributeMaxDynamicSharedMemorySize, smem_upd);

    k_prep<<<41, 256>>>(nk, attn);
    k_hist<<<(EE / 4 + 255) / 256, 256>>>((const int4*)dst);
    k_scan<<<1, 1024>>>();
    k_node<<<(NN + TRW - 1) / TRW, 256, smem_node>>>(h, W1, b1, W2, b2, attn);
    k_scatter<<<(EE / 4 + 255) / 256, 256>>>((const int4*)src, (const int4*)dst);
    k_edge<<<(NN * 32 + 255) / 256, 256>>>();
    k_upd<<<(NN + TRW - 1) / TRW, 256, smem_upd>>>(h, Wu, bu, Wr1, br1, Wr2, br2, out);
}